// round 8
// baseline (speedup 1.0000x reference)
#include <cuda_runtime.h>
#include <cstdint>

#define BB 2
#define SS 2048
#define DD 1024
#define HH 16
#define HDD 64
#define MTOT (BB * SS)

// Scratch
__device__ float g_q[BB * HH * SS * HDD];   // [b,h,s,hd]
__device__ float g_k[BB * HH * SS * HDD];   // [b,h,s,hd]
__device__ float g_vt[BB * HH * HDD * SS];  // [b,h,hd,s]
__device__ float g_ctx[MTOT * DD];          // [b,s,d]

// ---------------------------------------------------------------- helpers
__device__ __forceinline__ uint32_t f2tf32(float f) {
    uint32_t u;
    asm("cvt.rna.tf32.f32 %0, %1;" : "=r"(u) : "f"(f));
    return u;
}
__device__ __forceinline__ float ex2f(float x) {
    float r;
    asm("ex2.approx.f32 %0, %1;" : "=f"(r) : "f"(x));
    return r;
}
// m16n8k8 tf32 MMA: D += A*B, row.col. acc in d[4].
__device__ __forceinline__ void mma8(float* d, const uint32_t* a, uint32_t b0,
                                     uint32_t b1) {
    asm volatile(
        "mma.sync.aligned.m16n8k8.row.col.f32.tf32.tf32.f32 "
        "{%0,%1,%2,%3}, {%4,%5,%6,%7}, {%8,%9}, {%0,%1,%2,%3};"
        : "+f"(d[0]), "+f"(d[1]), "+f"(d[2]), "+f"(d[3])
        : "r"(a[0]), "r"(a[1]), "r"(a[2]), "r"(a[3]), "r"(b0), "r"(b1));
}

// ============================================================================
// Projection GEMM: C[M,N] = A[M,K] * W[N,K]^T via mma.sync tf32.
// 128x128 tile, BK=16, 256 thr (8 warps, 4x2), per-warp 32x64, 2 CTAs/SM.
// smem stride 20 floats (== 4 mod 32 -> conflict-free frag LDS).
// MODE 0: out[m][n]. MODE 1: [b,h,s,hd]. MODE 2: V^T [b,h,hd,s].
// ============================================================================
#define GSTR 20
#define GTILE (128 * GSTR)
#define PSMEM_G (4 * GTILE * 4)  // 40960 B

template <int MODE>
__global__ void __launch_bounds__(256, 2)
gemm_mma(const float* __restrict__ A, const float* __restrict__ W,
         float* __restrict__ out) {
    extern __shared__ uint32_t smg[];
    uint32_t* As[2] = {smg, smg + GTILE};
    uint32_t* Bs[2] = {smg + 2 * GTILE, smg + 3 * GTILE};

    const int tid = threadIdx.x;
    const int lane = tid & 31, wid = tid >> 5;
    const int gid = lane >> 2, tig = lane & 3;
    const int wm = wid & 3, wn = wid >> 2;
    const int m0 = blockIdx.y * 128, n0 = blockIdx.x * 128;

    const float* ap = A + (size_t)m0 * 1024;
    const float* wp = W + (size_t)n0 * 1024;

    // stage kt=0 (128 rows x 16 cols per matrix)
#pragma unroll
    for (int t = 0; t < 2; t++) {
        int idx = tid + t * 256;
        int r = idx >> 2, c = (idx & 3) * 4;
        float4 v = *(const float4*)(ap + (size_t)r * 1024 + c);
        uint4 u = make_uint4(f2tf32(v.x), f2tf32(v.y), f2tf32(v.z), f2tf32(v.w));
        *(uint4*)(As[0] + r * GSTR + c) = u;
        v = *(const float4*)(wp + (size_t)r * 1024 + c);
        u = make_uint4(f2tf32(v.x), f2tf32(v.y), f2tf32(v.z), f2tf32(v.w));
        *(uint4*)(Bs[0] + r * GSTR + c) = u;
    }
    __syncthreads();

    float acc[2][8][4];
#pragma unroll
    for (int i = 0; i < 2; i++)
#pragma unroll
        for (int j = 0; j < 8; j++)
#pragma unroll
            for (int q = 0; q < 4; q++) acc[i][j][q] = 0.f;

    float4 pfa[2], pfw[2];
    for (int kt = 0; kt < 64; kt++) {
        const int buf = kt & 1;
        if (kt + 1 < 64) {
            const float* a = ap + (kt + 1) * 16;
            const float* w = wp + (kt + 1) * 16;
#pragma unroll
            for (int t = 0; t < 2; t++) {
                int idx = tid + t * 256;
                int r = idx >> 2, c = (idx & 3) * 4;
                pfa[t] = *(const float4*)(a + (size_t)r * 1024 + c);
                pfw[t] = *(const float4*)(w + (size_t)r * 1024 + c);
            }
        }
        const uint32_t* Ab = As[buf];
        const uint32_t* Bb = Bs[buf];
#pragma unroll
        for (int ks = 0; ks < 2; ks++) {
            const int k = ks * 8;
            uint32_t a[2][4];
#pragma unroll
            for (int mt = 0; mt < 2; mt++) {
                int ar = (wm * 32 + mt * 16 + gid) * GSTR + k + tig;
                a[mt][0] = Ab[ar];
                a[mt][1] = Ab[ar + 8 * GSTR];
                a[mt][2] = Ab[ar + 4];
                a[mt][3] = Ab[ar + 8 * GSTR + 4];
            }
#pragma unroll
            for (int nt = 0; nt < 8; nt++) {
                int br = (wn * 64 + nt * 8 + gid) * GSTR + k + tig;
                uint32_t b0 = Bb[br], b1 = Bb[br + 4];
                mma8(acc[0][nt], a[0], b0, b1);
                mma8(acc[1][nt], a[1], b0, b1);
            }
        }
        if (kt + 1 < 64) {
            uint32_t* An = As[buf ^ 1];
            uint32_t* Bn = Bs[buf ^ 1];
            __syncthreads();  // everyone done reading buf^1 from kt-1
#pragma unroll
            for (int t = 0; t < 2; t++) {
                int idx = tid + t * 256;
                int r = idx >> 2, c = (idx & 3) * 4;
                uint4 u = make_uint4(f2tf32(pfa[t].x), f2tf32(pfa[t].y),
                                     f2tf32(pfa[t].z), f2tf32(pfa[t].w));
                *(uint4*)(An + r * GSTR + c) = u;
                u = make_uint4(f2tf32(pfw[t].x), f2tf32(pfw[t].y),
                               f2tf32(pfw[t].z), f2tf32(pfw[t].w));
                *(uint4*)(Bn + r * GSTR + c) = u;
            }
            __syncthreads();
        }
    }

    // epilogue
#pragma unroll
    for (int mt = 0; mt < 2; mt++)
#pragma unroll
        for (int hm = 0; hm < 2; hm++) {
            int mr = m0 + wm * 32 + mt * 16 + gid + hm * 8;
#pragma unroll
            for (int nt = 0; nt < 8; nt++) {
                int nc = n0 + wn * 64 + nt * 8 + 2 * tig;
                float2 v = make_float2(acc[mt][nt][hm * 2 + 0],
                                       acc[mt][nt][hm * 2 + 1]);
                if (MODE == 0) {
                    *(float2*)(out + (size_t)mr * 1024 + nc) = v;
                } else if (MODE == 1) {
                    int b = mr >> 11, s = mr & 2047;
                    int h = nc >> 6, hd = nc & 63;
                    *(float2*)(out + ((size_t)(b * HH + h) * SS + s) * HDD + hd) = v;
                } else {
                    int b = mr >> 11, s = mr & 2047;
                    int h = nc >> 6, hd = nc & 63;
                    float* dst = out + ((size_t)(b * HH + h) * HDD) * SS + s;
                    dst[(size_t)hd * SS] = v.x;
                    dst[(size_t)(hd + 1) * SS] = v.y;
                }
            }
        }
}

// ============================================================================
// Flash attention via mma.sync tf32. One block = 128 q-rows x one (b,h).
// 8 warps; warp w owns q-rows [w*16, w*16+16) x ALL 128 kv-cols.
// S computed in two 64-col chunks (acc 32 regs); fixed-max softmax
// (p = exp2((s+mask)*log2e/32)); P relayout acc->A-frag via quad shuffles
// (no smem round-trip); O += P*V in regs. 2 CTAs/SM (103.4KB smem, <=128 regs).
// ============================================================================
#define AQSTR 68   // 64-wide + 4
#define AVSTR 132  // 128-wide + 4
#define OFF_K (128 * AQSTR)
#define OFF_V (2 * 128 * AQSTR)
#define ASMEM_A ((OFF_V + 64 * AVSTR) * 4)  // 103424 B

__global__ void __launch_bounds__(256, 2)
attn_mma(const float* __restrict__ mask, float* __restrict__ ctx) {
    extern __shared__ uint32_t sma[];
    uint32_t* Qs = sma;
    uint32_t* Ks = sma + OFF_K;
    uint32_t* Vs = sma + OFF_V;

    const int tid = threadIdx.x;
    const int lane = tid & 31, wid = tid >> 5;
    const int gid = lane >> 2, tig = lane & 3;
    const int qt = blockIdx.x, bh = blockIdx.y;
    const int b = bh >> 4, h = bh & 15;

    const int r0 = wid * 16 + gid;   // this thread's even row
    const int r1 = r0 + 8;
    const int srcA = (lane & ~3) | (tig >> 1);
    const int srcB = srcA | 2;
    const int sel = tig & 1;

    const float* qg = g_q + ((size_t)bh * SS + qt * 128) * HDD;
    const float* kg = g_k + (size_t)bh * SS * HDD;
    const float* vg = g_vt + (size_t)bh * HDD * SS;

    // stage Q (128x64)
#pragma unroll
    for (int t = 0; t < 8; t++) {
        int idx = tid + t * 256;
        int r = idx >> 4, c = (idx & 15) * 4;
        float4 v = *(const float4*)(qg + (size_t)r * 64 + c);
        uint4 u = make_uint4(f2tf32(v.x), f2tf32(v.y), f2tf32(v.z), f2tf32(v.w));
        *(uint4*)(Qs + r * AQSTR + c) = u;
    }

    float o[8][4];
#pragma unroll
    for (int j = 0; j < 8; j++)
#pragma unroll
        for (int q = 0; q < 4; q++) o[j][q] = 0.f;
    float lsum0 = 0.f, lsum1 = 0.f;
    const float c2 = 1.4426950408889634f / 32.0f;  // log2(e)/sqrt(D)

    for (int nt = 0; nt < 16; nt++) {
        __syncthreads();  // prior iter done with Ks/Vs (covers Q stage at nt=0)
        // stage K (128x64)
#pragma unroll
        for (int t = 0; t < 8; t++) {
            int idx = tid + t * 256;
            int r = idx >> 4, c = (idx & 15) * 4;
            float4 v = *(const float4*)(kg + ((size_t)(nt * 128 + r)) * 64 + c);
            uint4 u = make_uint4(f2tf32(v.x), f2tf32(v.y), f2tf32(v.z), f2tf32(v.w));
            *(uint4*)(Ks + r * AQSTR + c) = u;
        }
        // stage V^T (64 hd x 128 s)
#pragma unroll
        for (int t = 0; t < 8; t++) {
            int idx = tid + t * 256;
            int r = idx >> 5, c = (idx & 31) * 4;
            float4 v = *(const float4*)(vg + (size_t)r * SS + nt * 128 + c);
            uint4 u = make_uint4(f2tf32(v.x), f2tf32(v.y), f2tf32(v.z), f2tf32(v.w));
            *(uint4*)(Vs + r * AVSTR + c) = u;
        }
        __syncthreads();

#pragma unroll
        for (int ch = 0; ch < 2; ch++) {
            // S chunk = Q(16 rows) x K(64 kv-rows)^T
            float s_[8][4];
#pragma unroll
            for (int j = 0; j < 8; j++)
#pragma unroll
                for (int q = 0; q < 4; q++) s_[j][q] = 0.f;

#pragma unroll
            for (int ks = 0; ks < 8; ks++) {
                const int k = ks * 8;
                uint32_t a[4];
                int ar = r0 * AQSTR + k + tig;
                a[0] = Qs[ar];
                a[1] = Qs[ar + 8 * AQSTR];
                a[2] = Qs[ar + 4];
                a[3] = Qs[ar + 8 * AQSTR + 4];
#pragma unroll
                for (int ntl = 0; ntl < 8; ntl++) {
                    int br = (ch * 64 + ntl * 8 + gid) * AQSTR + k + tig;
                    mma8(s_[ntl], a, Ks[br], Ks[br + 4]);
                }
            }

            // softmax (fixed max 0): p = exp2((s+mask)*c2), rna-rounded tf32
            const float* mrp0 =
                mask + (size_t)(qt * 128 + r0) * SS + nt * 128 + ch * 64;
            const float* mrp1 =
                mask + (size_t)(qt * 128 + r1) * SS + nt * 128 + ch * 64;
#pragma unroll
            for (int ntl = 0; ntl < 8; ntl++) {
                float2 m0 = *(const float2*)(mrp0 + ntl * 8 + 2 * tig);
                float2 m1 = *(const float2*)(mrp1 + ntl * 8 + 2 * tig);
                float p0 = ex2f((s_[ntl][0] + m0.x) * c2);
                float p1 = ex2f((s_[ntl][1] + m0.y) * c2);
                float p2 = ex2f((s_[ntl][2] + m1.x) * c2);
                float p3 = ex2f((s_[ntl][3] + m1.y) * c2);
                p0 = __uint_as_float(f2tf32(p0));
                p1 = __uint_as_float(f2tf32(p1));
                p2 = __uint_as_float(f2tf32(p2));
                p3 = __uint_as_float(f2tf32(p3));
                s_[ntl][0] = p0; s_[ntl][1] = p1;
                s_[ntl][2] = p2; s_[ntl][3] = p3;
                lsum0 += p0 + p1;
                lsum1 += p2 + p3;
            }

            // O += P V : relayout P acc->A-frag via quad shuffles, then MMA
#pragma unroll
            for (int j = 0; j < 8; j++) {
                float v0 = __shfl_sync(0xffffffffu, s_[j][0], srcA);
                float v1 = __shfl_sync(0xffffffffu, s_[j][1], srcA);
                float v2 = __shfl_sync(0xffffffffu, s_[j][2], srcA);
                float v3 = __shfl_sync(0xffffffffu, s_[j][3], srcA);
                float w0 = __shfl_sync(0xffffffffu, s_[j][0], srcB);
                float w1 = __shfl_sync(0xffffffffu, s_[j][1], srcB);
                float w2 = __shfl_sync(0xffffffffu, s_[j][2], srcB);
                float w3 = __shfl_sync(0xffffffffu, s_[j][3], srcB);
                uint32_t af[4];
                af[0] = __float_as_uint(sel ? v1 : v0);  // P[r0][8j+tig]
                af[1] = __float_as_uint(sel ? v3 : v2);  // P[r1][8j+tig]
                af[2] = __float_as_uint(sel ? w1 : w0);  // P[r0][8j+tig+4]
                af[3] = __float_as_uint(sel ? w3 : w2);  // P[r1][8j+tig+4]
                const int kk = ch * 64 + j * 8;
#pragma unroll
                for (int ntl = 0; ntl < 8; ntl++) {
                    int br = (ntl * 8 + gid) * AVSTR + kk + tig;
                    mma8(o[ntl], af, Vs[br], Vs[br + 4]);
                }
            }
        }
    }

    // reduce row sums within quad (each row fully owned by this warp)
    lsum0 += __shfl_xor_sync(0xffffffffu, lsum0, 1);
    lsum0 += __shfl_xor_sync(0xffffffffu, lsum0, 2);
    lsum1 += __shfl_xor_sync(0xffffffffu, lsum1, 1);
    lsum1 += __shfl_xor_sync(0xffffffffu, lsum1, 2);
    float inv0 = 1.0f / lsum0;
    float inv1 = 1.0f / lsum1;

    // write context [b,s,d]
    float* dst0 = ctx + ((size_t)(b * SS + qt * 128 + r0)) * DD + h * 64;
    float* dst1 = ctx + ((size_t)(b * SS + qt * 128 + r1)) * DD + h * 64;
#pragma unroll
    for (int ntl = 0; ntl < 8; ntl++) {
        *(float2*)(dst0 + ntl * 8 + 2 * tig) =
            make_float2(o[ntl][0] * inv0, o[ntl][1] * inv0);
        *(float2*)(dst1 + ntl * 8 + 2 * tig) =
            make_float2(o[ntl][2] * inv1, o[ntl][3] * inv1);
    }
}

// ============================================================================
// Launch
// ============================================================================
extern "C" void kernel_launch(void* const* d_in, const int* in_sizes, int n_in,
                              void* d_out, int out_size) {
    const float* x    = (const float*)d_in[0];
    const float* mask = (const float*)d_in[1];
    const float* Wq   = (const float*)d_in[2];
    const float* Wk   = (const float*)d_in[3];
    const float* Wv   = (const float*)d_in[4];
    const float* Wo   = (const float*)d_in[5];
    float* out = (float*)d_out;

    float *qp, *kp, *vtp, *cp;
    cudaGetSymbolAddress((void**)&qp, g_q);
    cudaGetSymbolAddress((void**)&kp, g_k);
    cudaGetSymbolAddress((void**)&vtp, g_vt);
    cudaGetSymbolAddress((void**)&cp, g_ctx);

    cudaFuncSetAttribute(gemm_mma<0>, cudaFuncAttributeMaxDynamicSharedMemorySize, PSMEM_G);
    cudaFuncSetAttribute(gemm_mma<1>, cudaFuncAttributeMaxDynamicSharedMemorySize, PSMEM_G);
    cudaFuncSetAttribute(gemm_mma<2>, cudaFuncAttributeMaxDynamicSharedMemorySize, PSMEM_G);
    cudaFuncSetAttribute(attn_mma, cudaFuncAttributeMaxDynamicSharedMemorySize, ASMEM_A);

    dim3 gg(DD / 128, MTOT / 128);  // (8, 32)
    gemm_mma<1><<<gg, 256, PSMEM_G>>>(x, Wq, qp);
    gemm_mma<1><<<gg, 256, PSMEM_G>>>(x, Wk, kp);
    gemm_mma<2><<<gg, 256, PSMEM_G>>>(x, Wv, vtp);

    attn_mma<<<dim3(SS / 128, BB * HH), 256, ASMEM_A>>>(mask, cp);

    gemm_mma<0><<<gg, 256, PSMEM_G>>>(cp, Wo, out);
}

// round 10
// speedup vs baseline: 1.1583x; 1.1583x over previous
#include <cuda_runtime.h>
#include <cstdint>

#define BB 2
#define SS 2048
#define DD 1024
#define HH 16
#define HDD 64
#define MTOT (BB * SS)

// Scratch
__device__ float g_q[BB * HH * SS * HDD];   // [b,h,s,hd]
__device__ float g_k[BB * HH * SS * HDD];   // [b,h,s,hd]
__device__ float g_vt[BB * HH * HDD * SS];  // [b,h,hd,s]
__device__ float g_ctx[MTOT * DD];          // [b,s,d]

// ---------------------------------------------------------------- helpers
__device__ __forceinline__ uint32_t f2tf32(float f) {
    uint32_t u;
    asm("cvt.rna.tf32.f32 %0, %1;" : "=r"(u) : "f"(f));
    return u;
}
__device__ __forceinline__ float ex2f(float x) {
    float r;
    asm("ex2.approx.f32 %0, %1;" : "=f"(r) : "f"(x));
    return r;
}
__device__ __forceinline__ uint32_t cvta_s(const void* p) {
    uint32_t a;
    asm("{ .reg .u64 t; cvta.to.shared.u64 t, %1; cvt.u32.u64 %0, t; }"
        : "=r"(a) : "l"(p));
    return a;
}
// m16n8k8 tf32 MMA: D += A*B, row.col. acc in d[4].
__device__ __forceinline__ void mma8(float* d, const uint32_t* a, uint32_t b0,
                                     uint32_t b1) {
    asm volatile(
        "mma.sync.aligned.m16n8k8.row.col.f32.tf32.tf32.f32 "
        "{%0,%1,%2,%3}, {%4,%5,%6,%7}, {%8,%9}, {%0,%1,%2,%3};"
        : "+f"(d[0]), "+f"(d[1]), "+f"(d[2]), "+f"(d[3])
        : "r"(a[0]), "r"(a[1]), "r"(a[2]), "r"(a[3]), "r"(b0), "r"(b1));
}
// ldmatrix x4 (b16 view of tf32): 4 8x(4 tf32) tiles -> 4 regs.
__device__ __forceinline__ void ldsm4(uint32_t* r, uint32_t addr) {
    asm volatile(
        "ldmatrix.sync.aligned.m8n8.x4.shared.b16 {%0,%1,%2,%3}, [%4];"
        : "=r"(r[0]), "=r"(r[1]), "=r"(r[2]), "=r"(r[3])
        : "r"(addr));
}

// ============================================================================
// Projection GEMM: C[M,N] = A[M,K] * W[N,K]^T via mma.sync tf32 + ldmatrix.
// 128x128 tile, BK=16, 256 thr (8 warps, 4x2), per-warp 32x64, 2 CTAs/SM.
// smem stride 20 floats (== 4 mod 32 -> conflict-free frag/ldmatrix access).
// MODE 0: out[m][n]. MODE 1: [b,h,s,hd]. MODE 2: V^T [b,h,hd,s].
// ============================================================================
#define GSTR 20
#define GTILE (128 * GSTR)
#define PSMEM_G (4 * GTILE * 4)  // 40960 B

template <int MODE>
__global__ void __launch_bounds__(256, 2)
gemm_mma(const float* __restrict__ A, const float* __restrict__ W,
         float* __restrict__ out) {
    extern __shared__ uint32_t smg[];
    uint32_t* As[2] = {smg, smg + GTILE};
    uint32_t* Bs[2] = {smg + 2 * GTILE, smg + 3 * GTILE};

    const int tid = threadIdx.x;
    const int lane = tid & 31, wid = tid >> 5;
    const int gid = lane >> 2, tig = lane & 3;
    const int wm = wid & 3, wn = wid >> 2;
    const int m0 = blockIdx.y * 128, n0 = blockIdx.x * 128;

    const float* ap = A + (size_t)m0 * 1024;
    const float* wp = W + (size_t)n0 * 1024;

    // ldmatrix per-lane base addresses (bytes)
    const uint32_t smb = cvta_s(smg);
    // A frag: row = wm*32 + mt*16 + (lane&15), col = 4*(lane>>4)
    const uint32_t aAddr =
        smb + ((wm * 32 + (lane & 15)) * GSTR + 4 * (lane >> 4)) * 4;
    // B frags (2 n-tiles): row = wn*64 + np*16 + 8*(lane>>4) + (lane&7),
    //                      col = 4*((lane>>3)&1)
    const uint32_t bAddr =
        smb + 2 * GTILE * 4 +
        ((wn * 64 + 8 * (lane >> 4) + (lane & 7)) * GSTR +
         4 * ((lane >> 3) & 1)) * 4;

    // stage kt=0 (128 rows x 16 cols per matrix)
#pragma unroll
    for (int t = 0; t < 2; t++) {
        int idx = tid + t * 256;
        int r = idx >> 2, c = (idx & 3) * 4;
        float4 v = *(const float4*)(ap + (size_t)r * 1024 + c);
        uint4 u = make_uint4(f2tf32(v.x), f2tf32(v.y), f2tf32(v.z), f2tf32(v.w));
        *(uint4*)(As[0] + r * GSTR + c) = u;
        v = *(const float4*)(wp + (size_t)r * 1024 + c);
        u = make_uint4(f2tf32(v.x), f2tf32(v.y), f2tf32(v.z), f2tf32(v.w));
        *(uint4*)(Bs[0] + r * GSTR + c) = u;
    }
    __syncthreads();

    float acc[2][8][4];
#pragma unroll
    for (int i = 0; i < 2; i++)
#pragma unroll
        for (int j = 0; j < 8; j++)
#pragma unroll
            for (int q = 0; q < 4; q++) acc[i][j][q] = 0.f;

    float4 pfa[2], pfw[2];
    for (int kt = 0; kt < 64; kt++) {
        const int buf = kt & 1;
        const uint32_t bufo = buf ? (uint32_t)(GTILE * 4) : 0u;
        if (kt + 1 < 64) {
            const float* a = ap + (kt + 1) * 16;
            const float* w = wp + (kt + 1) * 16;
#pragma unroll
            for (int t = 0; t < 2; t++) {
                int idx = tid + t * 256;
                int r = idx >> 2, c = (idx & 3) * 4;
                pfa[t] = *(const float4*)(a + (size_t)r * 1024 + c);
                pfw[t] = *(const float4*)(w + (size_t)r * 1024 + c);
            }
        }
#pragma unroll
        for (int ks = 0; ks < 2; ks++) {
            const uint32_t ko = ks * 32;  // 8 floats
            uint32_t a0f[4], a1f[4];
            ldsm4(a0f, aAddr + bufo + ko);
            ldsm4(a1f, aAddr + bufo + ko + 16 * GSTR * 4);
#pragma unroll
            for (int np = 0; np < 4; np++) {
                uint32_t bf[4];
                ldsm4(bf, bAddr + bufo + ko + np * 16 * GSTR * 4);
                mma8(acc[0][2 * np + 0], a0f, bf[0], bf[1]);
                mma8(acc[0][2 * np + 1], a0f, bf[2], bf[3]);
                mma8(acc[1][2 * np + 0], a1f, bf[0], bf[1]);
                mma8(acc[1][2 * np + 1], a1f, bf[2], bf[3]);
            }
        }
        if (kt + 1 < 64) {
            uint32_t* An = As[buf ^ 1];
            uint32_t* Bn = Bs[buf ^ 1];
            __syncthreads();  // everyone done reading buf^1 from kt-1
#pragma unroll
            for (int t = 0; t < 2; t++) {
                int idx = tid + t * 256;
                int r = idx >> 2, c = (idx & 3) * 4;
                uint4 u = make_uint4(f2tf32(pfa[t].x), f2tf32(pfa[t].y),
                                     f2tf32(pfa[t].z), f2tf32(pfa[t].w));
                *(uint4*)(An + r * GSTR + c) = u;
                u = make_uint4(f2tf32(pfw[t].x), f2tf32(pfw[t].y),
                               f2tf32(pfw[t].z), f2tf32(pfw[t].w));
                *(uint4*)(Bn + r * GSTR + c) = u;
            }
            __syncthreads();
        }
    }

    // epilogue
#pragma unroll
    for (int mt = 0; mt < 2; mt++)
#pragma unroll
        for (int hm = 0; hm < 2; hm++) {
            int mr = m0 + wm * 32 + mt * 16 + gid + hm * 8;
#pragma unroll
            for (int nt = 0; nt < 8; nt++) {
                int nc = n0 + wn * 64 + nt * 8 + 2 * tig;
                float2 v = make_float2(acc[mt][nt][hm * 2 + 0],
                                       acc[mt][nt][hm * 2 + 1]);
                if (MODE == 0) {
                    *(float2*)(out + (size_t)mr * 1024 + nc) = v;
                } else if (MODE == 1) {
                    int b = mr >> 11, s = mr & 2047;
                    int h = nc >> 6, hd = nc & 63;
                    *(float2*)(out + ((size_t)(b * HH + h) * SS + s) * HDD + hd) = v;
                } else {
                    int b = mr >> 11, s = mr & 2047;
                    int h = nc >> 6, hd = nc & 63;
                    float* dst = out + ((size_t)(b * HH + h) * HDD) * SS + s;
                    dst[(size_t)hd * SS] = v.x;
                    dst[(size_t)(hd + 1) * SS] = v.y;
                }
            }
        }
}

// ============================================================================
// Flash attention via mma.sync tf32 + ldmatrix. One block = 128 q-rows x (b,h).
// 8 warps; warp w owns q-rows [w*16, w*16+16) x ALL 128 kv-cols.
// S in two 64-col chunks; fixed-max softmax (p = exp2((s+mask)*log2e/32));
// P acc->A-frag via quad shuffles; O += P*V in regs. 2 CTAs/SM.
// ============================================================================
#define AQSTR 68   // 64-wide + 4
#define AVSTR 132  // 128-wide + 4
#define OFF_K (128 * AQSTR)
#define OFF_V (2 * 128 * AQSTR)
#define ASMEM_A ((OFF_V + 64 * AVSTR) * 4)  // 103424 B

__global__ void __launch_bounds__(256, 2)
attn_mma(const float* __restrict__ mask, float* __restrict__ ctx) {
    extern __shared__ uint32_t sma[];
    uint32_t* Qs = sma;
    uint32_t* Ks = sma + OFF_K;
    uint32_t* Vs = sma + OFF_V;

    const int tid = threadIdx.x;
    const int lane = tid & 31, wid = tid >> 5;
    const int gid = lane >> 2, tig = lane & 3;
    const int qt = blockIdx.x, bh = blockIdx.y;
    const int b = bh >> 4, h = bh & 15;

    const int r0 = wid * 16 + gid;   // this thread's even row
    const int r1 = r0 + 8;
    const int srcA = (lane & ~3) | (tig >> 1);
    const int srcB = srcA | 2;
    const int sel = tig & 1;

    const float* qg = g_q + ((size_t)bh * SS + qt * 128) * HDD;
    const float* kg = g_k + (size_t)bh * SS * HDD;
    const float* vg = g_vt + (size_t)bh * HDD * SS;

    // ldmatrix per-lane base addresses (bytes)
    const uint32_t smb = cvta_s(sma);
    const uint32_t qAddr =
        smb + ((wid * 16 + (lane & 15)) * AQSTR + 4 * (lane >> 4)) * 4;
    const uint32_t kAddr =
        smb + OFF_K * 4 +
        ((8 * (lane >> 4) + (lane & 7)) * AQSTR + 4 * ((lane >> 3) & 1)) * 4;
    const uint32_t vAddr =
        smb + OFF_V * 4 +
        ((8 * (lane >> 4) + (lane & 7)) * AVSTR + 4 * ((lane >> 3) & 1)) * 4;

    // stage Q (128x64)
#pragma unroll
    for (int t = 0; t < 8; t++) {
        int idx = tid + t * 256;
        int r = idx >> 4, c = (idx & 15) * 4;
        float4 v = *(const float4*)(qg + (size_t)r * 64 + c);
        uint4 u = make_uint4(f2tf32(v.x), f2tf32(v.y), f2tf32(v.z), f2tf32(v.w));
        *(uint4*)(Qs + r * AQSTR + c) = u;
    }

    float o[8][4];
#pragma unroll
    for (int j = 0; j < 8; j++)
#pragma unroll
        for (int q = 0; q < 4; q++) o[j][q] = 0.f;
    float lsum0 = 0.f, lsum1 = 0.f;
    const float c2 = 1.4426950408889634f / 32.0f;  // log2(e)/sqrt(D)

    for (int nt = 0; nt < 16; nt++) {
        __syncthreads();  // prior iter done with Ks/Vs (covers Q stage at nt=0)
        // stage K (128x64)
#pragma unroll
        for (int t = 0; t < 8; t++) {
            int idx = tid + t * 256;
            int r = idx >> 4, c = (idx & 15) * 4;
            float4 v = *(const float4*)(kg + ((size_t)(nt * 128 + r)) * 64 + c);
            uint4 u = make_uint4(f2tf32(v.x), f2tf32(v.y), f2tf32(v.z), f2tf32(v.w));
            *(uint4*)(Ks + r * AQSTR + c) = u;
        }
        // stage V^T (64 hd x 128 s)
#pragma unroll
        for (int t = 0; t < 8; t++) {
            int idx = tid + t * 256;
            int r = idx >> 5, c = (idx & 31) * 4;
            float4 v = *(const float4*)(vg + (size_t)r * SS + nt * 128 + c);
            uint4 u = make_uint4(f2tf32(v.x), f2tf32(v.y), f2tf32(v.z), f2tf32(v.w));
            *(uint4*)(Vs + r * AVSTR + c) = u;
        }
        __syncthreads();

#pragma unroll
        for (int ch = 0; ch < 2; ch++) {
            // S chunk = Q(16 rows) x K(64 kv-rows)^T
            float s_[8][4];
#pragma unroll
            for (int j = 0; j < 8; j++)
#pragma unroll
                for (int q = 0; q < 4; q++) s_[j][q] = 0.f;

            const uint32_t kChunk = kAddr + (uint32_t)(ch * 64 * AQSTR * 4);
#pragma unroll
            for (int ks = 0; ks < 8; ks++) {
                const uint32_t ko = ks * 32;
                uint32_t a[4];
                ldsm4(a, qAddr + ko);
#pragma unroll
                for (int np = 0; np < 4; np++) {
                    uint32_t bf[4];
                    ldsm4(bf, kChunk + ko + np * 16 * AQSTR * 4);
                    mma8(s_[2 * np + 0], a, bf[0], bf[1]);
                    mma8(s_[2 * np + 1], a, bf[2], bf[3]);
                }
            }

            // softmax (fixed max 0): p = exp2((s+mask)*c2), rna-rounded tf32
            const float* mrp0 =
                mask + (size_t)(qt * 128 + r0) * SS + nt * 128 + ch * 64;
            const float* mrp1 =
                mask + (size_t)(qt * 128 + r1) * SS + nt * 128 + ch * 64;
#pragma unroll
            for (int ntl = 0; ntl < 8; ntl++) {
                float2 m0 = *(const float2*)(mrp0 + ntl * 8 + 2 * tig);
                float2 m1 = *(const float2*)(mrp1 + ntl * 8 + 2 * tig);
                float p0 = ex2f((s_[ntl][0] + m0.x) * c2);
                float p1 = ex2f((s_[ntl][1] + m0.y) * c2);
                float p2 = ex2f((s_[ntl][2] + m1.x) * c2);
                float p3 = ex2f((s_[ntl][3] + m1.y) * c2);
                p0 = __uint_as_float(f2tf32(p0));
                p1 = __uint_as_float(f2tf32(p1));
                p2 = __uint_as_float(f2tf32(p2));
                p3 = __uint_as_float(f2tf32(p3));
                s_[ntl][0] = p0; s_[ntl][1] = p1;
                s_[ntl][2] = p2; s_[ntl][3] = p3;
                lsum0 += p0 + p1;
                lsum1 += p2 + p3;
            }

            // O += P V : relayout P acc->A-frag via quad shuffles, then MMA
#pragma unroll
            for (int j = 0; j < 8; j++) {
                float v0 = __shfl_sync(0xffffffffu, s_[j][0], srcA);
                float v1 = __shfl_sync(0xffffffffu, s_[j][1], srcA);
                float v2 = __shfl_sync(0xffffffffu, s_[j][2], srcA);
                float v3 = __shfl_sync(0xffffffffu, s_[j][3], srcA);
                float w0 = __shfl_sync(0xffffffffu, s_[j][0], srcB);
                float w1 = __shfl_sync(0xffffffffu, s_[j][1], srcB);
                float w2 = __shfl_sync(0xffffffffu, s_[j][2], srcB);
                float w3 = __shfl_sync(0xffffffffu, s_[j][3], srcB);
                uint32_t af[4];
                af[0] = __float_as_uint(sel ? v1 : v0);  // P[r0][8j+tig]
                af[1] = __float_as_uint(sel ? v3 : v2);  // P[r1][8j+tig]
                af[2] = __float_as_uint(sel ? w1 : w0);  // P[r0][8j+tig+4]
                af[3] = __float_as_uint(sel ? w3 : w2);  // P[r1][8j+tig+4]
                const uint32_t kko = (uint32_t)((ch * 64 + j * 8) * 4);
#pragma unroll
                for (int np = 0; np < 4; np++) {
                    uint32_t bf[4];
                    ldsm4(bf, vAddr + kko + np * 16 * AVSTR * 4);
                    mma8(o[2 * np + 0], af, bf[0], bf[1]);
                    mma8(o[2 * np + 1], af, bf[2], bf[3]);
                }
            }
        }
    }

    // reduce row sums within quad (each row fully owned by this warp)
    lsum0 += __shfl_xor_sync(0xffffffffu, lsum0, 1);
    lsum0 += __shfl_xor_sync(0xffffffffu, lsum0, 2);
    lsum1 += __shfl_xor_sync(0xffffffffu, lsum1, 1);
    lsum1 += __shfl_xor_sync(0xffffffffu, lsum1, 2);
    float inv0 = 1.0f / lsum0;
    float inv1 = 1.0f / lsum1;

    // write context [b,s,d]
    float* dst0 = ctx + ((size_t)(b * SS + qt * 128 + r0)) * DD + h * 64;
    float* dst1 = ctx + ((size_t)(b * SS + qt * 128 + r1)) * DD + h * 64;
#pragma unroll
    for (int ntl = 0; ntl < 8; ntl++) {
        *(float2*)(dst0 + ntl * 8 + 2 * tig) =
            make_float2(o[ntl][0] * inv0, o[ntl][1] * inv0);
        *(float2*)(dst1 + ntl * 8 + 2 * tig) =
            make_float2(o[ntl][2] * inv1, o[ntl][3] * inv1);
    }
}

// ============================================================================
// Launch
// ============================================================================
extern "C" void kernel_launch(void* const* d_in, const int* in_sizes, int n_in,
                              void* d_out, int out_size) {
    const float* x    = (const float*)d_in[0];
    const float* mask = (const float*)d_in[1];
    const float* Wq   = (const float*)d_in[2];
    const float* Wk   = (const float*)d_in[3];
    const float* Wv   = (const float*)d_in[4];
    const float* Wo   = (const float*)d_in[5];
    float* out = (float*)d_out;

    float *qp, *kp, *vtp, *cp;
    cudaGetSymbolAddress((void**)&qp, g_q);
    cudaGetSymbolAddress((void**)&kp, g_k);
    cudaGetSymbolAddress((void**)&vtp, g_vt);
    cudaGetSymbolAddress((void**)&cp, g_ctx);

    cudaFuncSetAttribute(gemm_mma<0>, cudaFuncAttributeMaxDynamicSharedMemorySize, PSMEM_G);
    cudaFuncSetAttribute(gemm_mma<1>, cudaFuncAttributeMaxDynamicSharedMemorySize, PSMEM_G);
    cudaFuncSetAttribute(gemm_mma<2>, cudaFuncAttributeMaxDynamicSharedMemorySize, PSMEM_G);
    cudaFuncSetAttribute(attn_mma, cudaFuncAttributeMaxDynamicSharedMemorySize, ASMEM_A);

    dim3 gg(DD / 128, MTOT / 128);  // (8, 32)
    gemm_mma<1><<<gg, 256, PSMEM_G>>>(x, Wq, qp);
    gemm_mma<1><<<gg, 256, PSMEM_G>>>(x, Wk, kp);
    gemm_mma<2><<<gg, 256, PSMEM_G>>>(x, Wv, vtp);

    attn_mma<<<dim3(SS / 128, BB * HH), 256, ASMEM_A>>>(mask, cp);

    gemm_mma<0><<<gg, 256, PSMEM_G>>>(cp, Wo, out);
}

// round 12
// speedup vs baseline: 1.5618x; 1.3484x over previous
#include <cuda_runtime.h>
#include <cuda_fp16.h>
#include <cstdint>

#define BB 2
#define SS 2048
#define DD 1024
#define HH 16
#define HDD 64
#define MTOT (BB * SS)

// Scratch
__device__ float g_q[BB * HH * SS * HDD];   // [b,h,s,hd]
__device__ float g_k[BB * HH * SS * HDD];   // [b,h,s,hd]
__device__ float g_vt[BB * HH * HDD * SS];  // [b,h,hd,s]
__device__ float g_ctx[MTOT * DD];          // [b,s,d]

// ---------------------------------------------------------------- helpers
__device__ __forceinline__ float ex2f(float x) {
    float r;
    asm("ex2.approx.f32 %0, %1;" : "=f"(r) : "f"(x));
    return r;
}
__device__ __forceinline__ uint32_t cvta_s(const void* p) {
    uint32_t a;
    asm("{ .reg .u64 t; cvta.to.shared.u64 t, %1; cvt.u32.u64 %0, t; }"
        : "=r"(a) : "l"(p));
    return a;
}
__device__ __forceinline__ uint32_t pk2(float lo, float hi) {
    __half2 h = __floats2half2_rn(lo, hi);
    return *reinterpret_cast<uint32_t*>(&h);
}
// m16n8k16 f16 MMA, fp32 accum: D += A*B (row.col).
__device__ __forceinline__ void mma16(float* d, const uint32_t* a, uint32_t b0,
                                      uint32_t b1) {
    asm volatile(
        "mma.sync.aligned.m16n8k16.row.col.f32.f16.f16.f32 "
        "{%0,%1,%2,%3}, {%4,%5,%6,%7}, {%8,%9}, {%0,%1,%2,%3};"
        : "+f"(d[0]), "+f"(d[1]), "+f"(d[2]), "+f"(d[3])
        : "r"(a[0]), "r"(a[1]), "r"(a[2]), "r"(a[3]), "r"(b0), "r"(b1));
}
// ldmatrix x4 b16: 4 8x8-fp16 tiles -> 4 regs.
__device__ __forceinline__ void ldsm4(uint32_t* r, uint32_t addr) {
    asm volatile(
        "ldmatrix.sync.aligned.m8n8.x4.shared.b16 {%0,%1,%2,%3}, [%4];"
        : "=r"(r[0]), "=r"(r[1]), "=r"(r[2]), "=r"(r[3])
        : "r"(addr));
}

// ============================================================================
// Projection GEMM: C[M,N] = A[M,K] * W[N,K]^T via mma.sync f16 + ldmatrix.
// 128x128 tile, BK=16, 256 thr (8 warps, 4x2), per-warp 32x64, 2 CTAs/SM.
// fp16 smem, row stride 24 halves (48B; 8-row ldmatrix addrs conflict-free).
// MODE 0: out[m][n]. MODE 1: [b,h,s,hd]. MODE 2: V^T [b,h,hd,s].
// ============================================================================
#define GSTR 24                  // halves per row
#define GTILE (128 * GSTR)       // halves per tile
#define PSMEM_G (4 * GTILE * 2)  // 24576 B

template <int MODE>
__global__ void __launch_bounds__(256, 2)
gemm_mma(const float* __restrict__ A, const float* __restrict__ W,
         float* __restrict__ out) {
    extern __shared__ __half smh[];
    __half* As[2] = {smh, smh + GTILE};
    __half* Bs[2] = {smh + 2 * GTILE, smh + 3 * GTILE};

    const int tid = threadIdx.x;
    const int lane = tid & 31, wid = tid >> 5;
    const int gid = lane >> 2, tig = lane & 3;
    const int wm = wid & 3, wn = wid >> 2;
    const int m0 = blockIdx.y * 128, n0 = blockIdx.x * 128;

    const float* ap = A + (size_t)m0 * 1024;
    const float* wp = W + (size_t)n0 * 1024;

    // ldmatrix per-lane base addresses (bytes)
    const uint32_t smb = cvta_s(smh);
    const uint32_t aAddr =
        smb + ((wm * 32 + (lane & 15)) * GSTR + 8 * (lane >> 4)) * 2;
    const uint32_t bAddr =
        smb + 2 * GTILE * 2 +
        ((wn * 64 + (lane & 7) + 8 * (lane >> 4)) * GSTR +
         8 * ((lane >> 3) & 1)) * 2;

    const int sr = tid >> 1, shf = tid & 1;  // stage: row, col-half

    // stage kt=0 (128 rows x 16 cols per matrix)
    {
        float4 v1 = *(const float4*)(ap + (size_t)sr * 1024 + shf * 8);
        float4 v2 = *(const float4*)(ap + (size_t)sr * 1024 + shf * 8 + 4);
        uint4 u = make_uint4(pk2(v1.x, v1.y), pk2(v1.z, v1.w),
                             pk2(v2.x, v2.y), pk2(v2.z, v2.w));
        *(uint4*)(As[0] + sr * GSTR + shf * 8) = u;
        v1 = *(const float4*)(wp + (size_t)sr * 1024 + shf * 8);
        v2 = *(const float4*)(wp + (size_t)sr * 1024 + shf * 8 + 4);
        u = make_uint4(pk2(v1.x, v1.y), pk2(v1.z, v1.w),
                       pk2(v2.x, v2.y), pk2(v2.z, v2.w));
        *(uint4*)(Bs[0] + sr * GSTR + shf * 8) = u;
    }
    __syncthreads();

    float acc[2][8][4];
#pragma unroll
    for (int i = 0; i < 2; i++)
#pragma unroll
        for (int j = 0; j < 8; j++)
#pragma unroll
            for (int q = 0; q < 4; q++) acc[i][j][q] = 0.f;

    float4 pfa[2], pfw[2];
    for (int kt = 0; kt < 64; kt++) {
        const int buf = kt & 1;
        const uint32_t bufo = buf ? (uint32_t)(GTILE * 2) : 0u;
        if (kt + 1 < 64) {
            const float* a = ap + (kt + 1) * 16;
            const float* w = wp + (kt + 1) * 16;
            pfa[0] = *(const float4*)(a + (size_t)sr * 1024 + shf * 8);
            pfa[1] = *(const float4*)(a + (size_t)sr * 1024 + shf * 8 + 4);
            pfw[0] = *(const float4*)(w + (size_t)sr * 1024 + shf * 8);
            pfw[1] = *(const float4*)(w + (size_t)sr * 1024 + shf * 8 + 4);
        }
        uint32_t a0f[4], a1f[4];
        ldsm4(a0f, aAddr + bufo);
        ldsm4(a1f, aAddr + bufo + 16 * GSTR * 2);
#pragma unroll
        for (int np = 0; np < 4; np++) {
            uint32_t bf[4];
            ldsm4(bf, bAddr + bufo + np * 16 * GSTR * 2);
            mma16(acc[0][2 * np + 0], a0f, bf[0], bf[1]);
            mma16(acc[0][2 * np + 1], a0f, bf[2], bf[3]);
            mma16(acc[1][2 * np + 0], a1f, bf[0], bf[1]);
            mma16(acc[1][2 * np + 1], a1f, bf[2], bf[3]);
        }
        if (kt + 1 < 64) {
            __half* An = As[buf ^ 1];
            __half* Bn = Bs[buf ^ 1];
            __syncthreads();  // everyone done reading buf^1 from kt-1
            uint4 u = make_uint4(pk2(pfa[0].x, pfa[0].y), pk2(pfa[0].z, pfa[0].w),
                                 pk2(pfa[1].x, pfa[1].y), pk2(pfa[1].z, pfa[1].w));
            *(uint4*)(An + sr * GSTR + shf * 8) = u;
            u = make_uint4(pk2(pfw[0].x, pfw[0].y), pk2(pfw[0].z, pfw[0].w),
                           pk2(pfw[1].x, pfw[1].y), pk2(pfw[1].z, pfw[1].w));
            *(uint4*)(Bn + sr * GSTR + shf * 8) = u;
            __syncthreads();
        }
    }

    // epilogue
#pragma unroll
    for (int mt = 0; mt < 2; mt++)
#pragma unroll
        for (int hm = 0; hm < 2; hm++) {
            int mr = m0 + wm * 32 + mt * 16 + gid + hm * 8;
#pragma unroll
            for (int nt = 0; nt < 8; nt++) {
                int nc = n0 + wn * 64 + nt * 8 + 2 * tig;
                float2 v = make_float2(acc[mt][nt][hm * 2 + 0],
                                       acc[mt][nt][hm * 2 + 1]);
                if (MODE == 0) {
                    *(float2*)(out + (size_t)mr * 1024 + nc) = v;
                } else if (MODE == 1) {
                    int b = mr >> 11, s = mr & 2047;
                    int h = nc >> 6, hd = nc & 63;
                    *(float2*)(out + ((size_t)(b * HH + h) * SS + s) * HDD + hd) = v;
                } else {
                    int b = mr >> 11, s = mr & 2047;
                    int h = nc >> 6, hd = nc & 63;
                    float* dst = out + ((size_t)(b * HH + h) * HDD) * SS + s;
                    dst[(size_t)hd * SS] = v.x;
                    dst[(size_t)(hd + 1) * SS] = v.y;
                }
            }
        }
}

// ============================================================================
// Flash attention via mma.sync f16 + ldmatrix. One block = 128 q-rows x (b,h).
// 8 warps; warp w owns q-rows [w*16, w*16+16) x ALL 128 kv-cols.
// S in two 64-col chunks (m16n8k16, fp32 acc); fixed-max softmax
// (p = exp2((s+mask)*log2e/32), rne-rounded to fp16, sums of rounded values);
// P accumulator pairs ARE the f16 A-fragment (no shuffles); O += P*V.
// fp16 smem (Q/K stride 72, V^T stride 136). 2 CTAs/SM.
// ============================================================================
#define AQSTR 72    // halves
#define AVSTR 136   // halves
#define OFF_K (128 * AQSTR)
#define OFF_V (2 * 128 * AQSTR)
#define ASMEM_A ((OFF_V + 64 * AVSTR) * 2)  // 54272 B

__global__ void __launch_bounds__(256, 2)
attn_mma(const float* __restrict__ mask, float* __restrict__ ctx) {
    extern __shared__ __half sma[];
    __half* Qs = sma;
    __half* Ks = sma + OFF_K;
    __half* Vs = sma + OFF_V;

    const int tid = threadIdx.x;
    const int lane = tid & 31, wid = tid >> 5;
    const int gid = lane >> 2, tig = lane & 3;
    const int qt = blockIdx.x, bh = blockIdx.y;
    const int b = bh >> 4, h = bh & 15;

    const int r0 = wid * 16 + gid;  // this thread's even row
    const int r1 = r0 + 8;

    const float* qg = g_q + ((size_t)bh * SS + qt * 128) * HDD;
    const float* kg = g_k + (size_t)bh * SS * HDD;
    const float* vg = g_vt + (size_t)bh * HDD * SS;

    // ldmatrix per-lane base addresses (bytes)
    const uint32_t smb = cvta_s(sma);
    const uint32_t qAddr =
        smb + ((wid * 16 + (lane & 15)) * AQSTR + 8 * (lane >> 4)) * 2;
    const uint32_t kAddr =
        smb + OFF_K * 2 +
        (((lane & 7) + 8 * (lane >> 4)) * AQSTR + 8 * ((lane >> 3) & 1)) * 2;
    const uint32_t vAddr =
        smb + OFF_V * 2 +
        (((lane & 7) + 8 * (lane >> 4)) * AVSTR + 8 * ((lane >> 3) & 1)) * 2;

    // stage Q (128x64 -> fp16)
#pragma unroll
    for (int t = 0; t < 4; t++) {
        int idx = tid + t * 256;
        int r = idx >> 3, c8 = (idx & 7) * 8;
        float4 v1 = *(const float4*)(qg + (size_t)r * 64 + c8);
        float4 v2 = *(const float4*)(qg + (size_t)r * 64 + c8 + 4);
        uint4 u = make_uint4(pk2(v1.x, v1.y), pk2(v1.z, v1.w),
                             pk2(v2.x, v2.y), pk2(v2.z, v2.w));
        *(uint4*)(Qs + r * AQSTR + c8) = u;
    }

    float o[8][4];
#pragma unroll
    for (int j = 0; j < 8; j++)
#pragma unroll
        for (int q = 0; q < 4; q++) o[j][q] = 0.f;
    float lsum0 = 0.f, lsum1 = 0.f;
    const float c2 = 1.4426950408889634f / 32.0f;  // log2(e)/sqrt(D)

    for (int nt = 0; nt < 16; nt++) {
        __syncthreads();  // prior iter done with Ks/Vs (covers Q stage at nt=0)
        // stage K (128x64)
#pragma unroll
        for (int t = 0; t < 4; t++) {
            int idx = tid + t * 256;
            int r = idx >> 3, c8 = (idx & 7) * 8;
            const float* src = kg + ((size_t)(nt * 128 + r)) * 64 + c8;
            float4 v1 = *(const float4*)(src);
            float4 v2 = *(const float4*)(src + 4);
            uint4 u = make_uint4(pk2(v1.x, v1.y), pk2(v1.z, v1.w),
                                 pk2(v2.x, v2.y), pk2(v2.z, v2.w));
            *(uint4*)(Ks + r * AQSTR + c8) = u;
        }
        // stage V^T (64 hd x 128 s)
#pragma unroll
        for (int t = 0; t < 4; t++) {
            int idx = tid + t * 256;
            int r = idx >> 4, c8 = (idx & 15) * 8;
            const float* src = vg + (size_t)r * SS + nt * 128 + c8;
            float4 v1 = *(const float4*)(src);
            float4 v2 = *(const float4*)(src + 4);
            uint4 u = make_uint4(pk2(v1.x, v1.y), pk2(v1.z, v1.w),
                                 pk2(v2.x, v2.y), pk2(v2.z, v2.w));
            *(uint4*)(Vs + r * AVSTR + c8) = u;
        }
        __syncthreads();

#pragma unroll
        for (int ch = 0; ch < 2; ch++) {
            // S chunk = Q(16 rows) x K(64 kv-rows)^T, K-dim 64 = 4 k16 steps
            float s_[8][4];
#pragma unroll
            for (int j = 0; j < 8; j++)
#pragma unroll
                for (int q = 0; q < 4; q++) s_[j][q] = 0.f;

            const uint32_t kChunk = kAddr + (uint32_t)(ch * 64 * AQSTR * 2);
#pragma unroll
            for (int ks = 0; ks < 4; ks++) {
                uint32_t a[4];
                ldsm4(a, qAddr + ks * 32);
#pragma unroll
                for (int np = 0; np < 4; np++) {
                    uint32_t bf[4];
                    ldsm4(bf, kChunk + ks * 32 + np * 16 * AQSTR * 2);
                    mma16(s_[2 * np + 0], a, bf[0], bf[1]);
                    mma16(s_[2 * np + 1], a, bf[2], bf[3]);
                }
            }

            // softmax (fixed max 0): p = exp2((s+mask)*c2) -> fp16 (rne).
            // Sum the ROUNDED values so normalization stays consistent.
            const float* mrp0 =
                mask + (size_t)(qt * 128 + r0) * SS + nt * 128 + ch * 64;
            const float* mrp1 =
                mask + (size_t)(qt * 128 + r1) * SS + nt * 128 + ch * 64;
            uint32_t ph[8][2];
#pragma unroll
            for (int ntl = 0; ntl < 8; ntl++) {
                float2 m0 = *(const float2*)(mrp0 + ntl * 8 + 2 * tig);
                float2 m1 = *(const float2*)(mrp1 + ntl * 8 + 2 * tig);
                float p0 = ex2f((s_[ntl][0] + m0.x) * c2);
                float p1 = ex2f((s_[ntl][1] + m0.y) * c2);
                float p2 = ex2f((s_[ntl][2] + m1.x) * c2);
                float p3 = ex2f((s_[ntl][3] + m1.y) * c2);
                __half2 h01 = __floats2half2_rn(p0, p1);
                __half2 h23 = __floats2half2_rn(p2, p3);
                ph[ntl][0] = *reinterpret_cast<uint32_t*>(&h01);
                ph[ntl][1] = *reinterpret_cast<uint32_t*>(&h23);
                float2 f01 = __half22float2(h01);
                float2 f23 = __half22float2(h23);
                lsum0 += f01.x + f01.y;
                lsum1 += f23.x + f23.y;
            }

            // O += P V : P accumulator pairs are already the f16 A-fragment.
#pragma unroll
            for (int j = 0; j < 4; j++) {
                uint32_t af[4];
                af[0] = ph[2 * j][0];      // (r0, k=16j+2tig,+1)
                af[1] = ph[2 * j][1];      // (r1, same k)
                af[2] = ph[2 * j + 1][0];  // (r0, k+8)
                af[3] = ph[2 * j + 1][1];  // (r1, k+8)
                const uint32_t kko = (uint32_t)((ch * 64 + 16 * j) * 2);
#pragma unroll
                for (int np = 0; np < 4; np++) {
                    uint32_t bf[4];
                    ldsm4(bf, vAddr + kko + np * 16 * AVSTR * 2);
                    mma16(o[2 * np + 0], af, bf[0], bf[1]);
                    mma16(o[2 * np + 1], af, bf[2], bf[3]);
                }
            }
        }
    }

    // reduce row sums within quad (each row fully owned by this warp)
    lsum0 += __shfl_xor_sync(0xffffffffu, lsum0, 1);
    lsum0 += __shfl_xor_sync(0xffffffffu, lsum0, 2);
    lsum1 += __shfl_xor_sync(0xffffffffu, lsum1, 1);
    lsum1 += __shfl_xor_sync(0xffffffffu, lsum1, 2);
    float inv0 = 1.0f / lsum0;
    float inv1 = 1.0f / lsum1;

    // write context [b,s,d]
    float* dst0 = ctx + ((size_t)(b * SS + qt * 128 + r0)) * DD + h * 64;
    float* dst1 = ctx + ((size_t)(b * SS + qt * 128 + r1)) * DD + h * 64;
#pragma unroll
    for (int ntl = 0; ntl < 8; ntl++) {
        *(float2*)(dst0 + ntl * 8 + 2 * tig) =
            make_float2(o[ntl][0] * inv0, o[ntl][1] * inv0);
        *(float2*)(dst1 + ntl * 8 + 2 * tig) =
            make_float2(o[ntl][2] * inv1, o[ntl][3] * inv1);
    }
}

// ============================================================================
// Launch
// ============================================================================
extern "C" void kernel_launch(void* const* d_in, const int* in_sizes, int n_in,
                              void* d_out, int out_size) {
    const float* x    = (const float*)d_in[0];
    const float* mask = (const float*)d_in[1];
    const float* Wq   = (const float*)d_in[2];
    const float* Wk   = (const float*)d_in[3];
    const float* Wv   = (const float*)d_in[4];
    const float* Wo   = (const float*)d_in[5];
    float* out = (float*)d_out;

    float *qp, *kp, *vtp, *cp;
    cudaGetSymbolAddress((void**)&qp, g_q);
    cudaGetSymbolAddress((void**)&kp, g_k);
    cudaGetSymbolAddress((void**)&vtp, g_vt);
    cudaGetSymbolAddress((void**)&cp, g_ctx);

    cudaFuncSetAttribute(gemm_mma<0>, cudaFuncAttributeMaxDynamicSharedMemorySize, PSMEM_G);
    cudaFuncSetAttribute(gemm_mma<1>, cudaFuncAttributeMaxDynamicSharedMemorySize, PSMEM_G);
    cudaFuncSetAttribute(gemm_mma<2>, cudaFuncAttributeMaxDynamicSharedMemorySize, PSMEM_G);
    cudaFuncSetAttribute(attn_mma, cudaFuncAttributeMaxDynamicSharedMemorySize, ASMEM_A);

    dim3 gg(DD / 128, MTOT / 128);  // (8, 32)
    gemm_mma<1><<<gg, 256, PSMEM_G>>>(x, Wq, qp);
    gemm_mma<1><<<gg, 256, PSMEM_G>>>(x, Wk, kp);
    gemm_mma<2><<<gg, 256, PSMEM_G>>>(x, Wv, vtp);

    attn_mma<<<dim3(SS / 128, BB * HH), 256, ASMEM_A>>>(mask, cp);

    gemm_mma<0><<<gg, 256, PSMEM_G>>>(cp, Wo, out);
}

// round 14
// speedup vs baseline: 1.6501x; 1.0565x over previous
#include <cuda_runtime.h>
#include <cuda_fp16.h>
#include <cstdint>

#define BB 2
#define SS 2048
#define DD 1024
#define HH 16
#define HDD 64
#define MTOT (BB * SS)

// Scratch (fp32, as in R12)
__device__ float g_q[BB * HH * SS * HDD];   // [b,h,s,hd]
__device__ float g_k[BB * HH * SS * HDD];   // [b,h,s,hd]
__device__ float g_vt[BB * HH * HDD * SS];  // [b,h,hd,s]
__device__ float g_ctx[MTOT * DD];          // [b,s,d]

// ---------------------------------------------------------------- helpers
__device__ __forceinline__ float ex2f(float x) {
    float r;
    asm("ex2.approx.f32 %0, %1;" : "=f"(r) : "f"(x));
    return r;
}
__device__ __forceinline__ uint32_t cvta_s(const void* p) {
    uint32_t a;
    asm("{ .reg .u64 t; cvta.to.shared.u64 t, %1; cvt.u32.u64 %0, t; }"
        : "=r"(a) : "l"(p));
    return a;
}
__device__ __forceinline__ uint32_t pk2(float lo, float hi) {
    __half2 h = __floats2half2_rn(lo, hi);
    return *reinterpret_cast<uint32_t*>(&h);
}
// m16n8k16 f16 MMA, fp32 accum: D += A*B (row.col).
__device__ __forceinline__ void mma16(float* d, const uint32_t* a, uint32_t b0,
                                      uint32_t b1) {
    asm volatile(
        "mma.sync.aligned.m16n8k16.row.col.f32.f16.f16.f32 "
        "{%0,%1,%2,%3}, {%4,%5,%6,%7}, {%8,%9}, {%0,%1,%2,%3};"
        : "+f"(d[0]), "+f"(d[1]), "+f"(d[2]), "+f"(d[3])
        : "r"(a[0]), "r"(a[1]), "r"(a[2]), "r"(a[3]), "r"(b0), "r"(b1));
}
// ldmatrix x4 b16: 4 8x8-fp16 tiles -> 4 regs.
__device__ __forceinline__ void ldsm4(uint32_t* r, uint32_t addr) {
    asm volatile(
        "ldmatrix.sync.aligned.m8n8.x4.shared.b16 {%0,%1,%2,%3}, [%4];"
        : "=r"(r[0]), "=r"(r[1]), "=r"(r[2]), "=r"(r[3])
        : "r"(addr));
}

// ============================================================================
// Projection GEMM (unchanged from R12): C = A * W^T via mma16 + ldmatrix.
// 128x128 tile, BK=16, 256 thr (8 warps, 4x2), per-warp 32x64, 2 CTAs/SM.
// fp16 smem, row stride 24 halves.
// MODE 0: out[m][n]. MODE 1: [b,h,s,hd]. MODE 2: V^T [b,h,hd,s].
// ============================================================================
#define GSTR 24                  // halves per row
#define GTILE (128 * GSTR)       // halves per tile
#define PSMEM_G (4 * GTILE * 2)  // 24576 B

template <int MODE>
__global__ void __launch_bounds__(256, 2)
gemm_mma(const float* __restrict__ A, const float* __restrict__ W,
         float* __restrict__ out) {
    extern __shared__ __half smh[];
    __half* As[2] = {smh, smh + GTILE};
    __half* Bs[2] = {smh + 2 * GTILE, smh + 3 * GTILE};

    const int tid = threadIdx.x;
    const int lane = tid & 31, wid = tid >> 5;
    const int gid = lane >> 2, tig = lane & 3;
    const int wm = wid & 3, wn = wid >> 2;
    const int m0 = blockIdx.y * 128, n0 = blockIdx.x * 128;

    const float* ap = A + (size_t)m0 * 1024;
    const float* wp = W + (size_t)n0 * 1024;

    const uint32_t smb = cvta_s(smh);
    const uint32_t aAddr =
        smb + ((wm * 32 + (lane & 15)) * GSTR + 8 * (lane >> 4)) * 2;
    const uint32_t bAddr =
        smb + 2 * GTILE * 2 +
        ((wn * 64 + (lane & 7) + 8 * (lane >> 4)) * GSTR +
         8 * ((lane >> 3) & 1)) * 2;

    const int sr = tid >> 1, shf = tid & 1;  // stage: row, col-half

    // stage kt=0 (128 rows x 16 cols per matrix)
    {
        float4 v1 = *(const float4*)(ap + (size_t)sr * 1024 + shf * 8);
        float4 v2 = *(const float4*)(ap + (size_t)sr * 1024 + shf * 8 + 4);
        uint4 u = make_uint4(pk2(v1.x, v1.y), pk2(v1.z, v1.w),
                             pk2(v2.x, v2.y), pk2(v2.z, v2.w));
        *(uint4*)(As[0] + sr * GSTR + shf * 8) = u;
        v1 = *(const float4*)(wp + (size_t)sr * 1024 + shf * 8);
        v2 = *(const float4*)(wp + (size_t)sr * 1024 + shf * 8 + 4);
        u = make_uint4(pk2(v1.x, v1.y), pk2(v1.z, v1.w),
                       pk2(v2.x, v2.y), pk2(v2.z, v2.w));
        *(uint4*)(Bs[0] + sr * GSTR + shf * 8) = u;
    }
    __syncthreads();

    float acc[2][8][4];
#pragma unroll
    for (int i = 0; i < 2; i++)
#pragma unroll
        for (int j = 0; j < 8; j++)
#pragma unroll
            for (int q = 0; q < 4; q++) acc[i][j][q] = 0.f;

    float4 pfa[2], pfw[2];
    for (int kt = 0; kt < 64; kt++) {
        const int buf = kt & 1;
        const uint32_t bufo = buf ? (uint32_t)(GTILE * 2) : 0u;
        if (kt + 1 < 64) {
            const float* a = ap + (kt + 1) * 16;
            const float* w = wp + (kt + 1) * 16;
            pfa[0] = *(const float4*)(a + (size_t)sr * 1024 + shf * 8);
            pfa[1] = *(const float4*)(a + (size_t)sr * 1024 + shf * 8 + 4);
            pfw[0] = *(const float4*)(w + (size_t)sr * 1024 + shf * 8);
            pfw[1] = *(const float4*)(w + (size_t)sr * 1024 + shf * 8 + 4);
        }
        uint32_t a0f[4], a1f[4];
        ldsm4(a0f, aAddr + bufo);
        ldsm4(a1f, aAddr + bufo + 16 * GSTR * 2);
#pragma unroll
        for (int np = 0; np < 4; np++) {
            uint32_t bf[4];
            ldsm4(bf, bAddr + bufo + np * 16 * GSTR * 2);
            mma16(acc[0][2 * np + 0], a0f, bf[0], bf[1]);
            mma16(acc[0][2 * np + 1], a0f, bf[2], bf[3]);
            mma16(acc[1][2 * np + 0], a1f, bf[0], bf[1]);
            mma16(acc[1][2 * np + 1], a1f, bf[2], bf[3]);
        }
        if (kt + 1 < 64) {
            __half* An = As[buf ^ 1];
            __half* Bn = Bs[buf ^ 1];
            __syncthreads();  // everyone done reading buf^1 from kt-1
            uint4 u = make_uint4(pk2(pfa[0].x, pfa[0].y), pk2(pfa[0].z, pfa[0].w),
                                 pk2(pfa[1].x, pfa[1].y), pk2(pfa[1].z, pfa[1].w));
            *(uint4*)(An + sr * GSTR + shf * 8) = u;
            u = make_uint4(pk2(pfw[0].x, pfw[0].y), pk2(pfw[0].z, pfw[0].w),
                           pk2(pfw[1].x, pfw[1].y), pk2(pfw[1].z, pfw[1].w));
            *(uint4*)(Bn + sr * GSTR + shf * 8) = u;
            __syncthreads();
        }
    }

    // epilogue
#pragma unroll
    for (int mt = 0; mt < 2; mt++)
#pragma unroll
        for (int hm = 0; hm < 2; hm++) {
            int mr = m0 + wm * 32 + mt * 16 + gid + hm * 8;
#pragma unroll
            for (int nt = 0; nt < 8; nt++) {
                int nc = n0 + wn * 64 + nt * 8 + 2 * tig;
                float2 v = make_float2(acc[mt][nt][hm * 2 + 0],
                                       acc[mt][nt][hm * 2 + 1]);
                if (MODE == 0) {
                    *(float2*)(out + (size_t)mr * 1024 + nc) = v;
                } else if (MODE == 1) {
                    int b = mr >> 11, s = mr & 2047;
                    int h = nc >> 6, hd = nc & 63;
                    *(float2*)(out + ((size_t)(b * HH + h) * SS + s) * HDD + hd) = v;
                } else {
                    int b = mr >> 11, s = mr & 2047;
                    int h = nc >> 6, hd = nc & 63;
                    float* dst = out + ((size_t)(b * HH + h) * HDD) * SS + s;
                    dst[(size_t)hd * SS] = v.x;
                    dst[(size_t)(hd + 1) * SS] = v.y;
                }
            }
        }
}

// ============================================================================
// Flash attention via mma.sync f16 + ldmatrix. One block = 128 q-rows x (b,h).
// 128 threads (4 warps); warp w owns 32 q-rows [w*32, w*32+32) x 128 kv-cols:
// every K/V B-fragment feeds BOTH 16-row A tiles (2x FLOP per smem byte vs R12).
// Staging, layouts, numerics identical to R12 (fixed-max softmax,
// p = exp2((s+mask)*log2e/32) -> fp16 rne, sums of rounded values,
// P accumulator pairs are the f16 A-fragment).
// ============================================================================
#define AQSTR 72    // halves
#define AVSTR 136   // halves
#define OFF_K (128 * AQSTR)
#define OFF_V (2 * 128 * AQSTR)
#define ASMEM_A ((OFF_V + 64 * AVSTR) * 2)  // 54272 B

__global__ void __launch_bounds__(128)
attn_mma(const float* __restrict__ mask, float* __restrict__ ctx) {
    extern __shared__ __half sma[];
    __half* Qs = sma;
    __half* Ks = sma + OFF_K;
    __half* Vs = sma + OFF_V;

    const int tid = threadIdx.x;
    const int lane = tid & 31, wid = tid >> 5;
    const int gid = lane >> 2, tig = lane & 3;
    const int qt = blockIdx.x, bh = blockIdx.y;
    const int b = bh >> 4, h = bh & 15;

    const float* qg = g_q + ((size_t)bh * SS + qt * 128) * HDD;
    const float* kg = g_k + (size_t)bh * SS * HDD;
    const float* vg = g_vt + (size_t)bh * HDD * SS;

    // ldmatrix per-lane base addresses (bytes)
    const uint32_t smb = cvta_s(sma);
    const uint32_t qAddr =
        smb + ((wid * 32 + (lane & 15)) * AQSTR + 8 * (lane >> 4)) * 2;
    const uint32_t kAddr =
        smb + OFF_K * 2 +
        (((lane & 7) + 8 * (lane >> 4)) * AQSTR + 8 * ((lane >> 3) & 1)) * 2;
    const uint32_t vAddr =
        smb + OFF_V * 2 +
        (((lane & 7) + 8 * (lane >> 4)) * AVSTR + 8 * ((lane >> 3) & 1)) * 2;

    // stage Q (128x64 -> fp16), 128 threads
#pragma unroll
    for (int t = 0; t < 8; t++) {
        int idx = tid + t * 128;
        int r = idx >> 3, c8 = (idx & 7) * 8;
        float4 v1 = *(const float4*)(qg + (size_t)r * 64 + c8);
        float4 v2 = *(const float4*)(qg + (size_t)r * 64 + c8 + 4);
        uint4 u = make_uint4(pk2(v1.x, v1.y), pk2(v1.z, v1.w),
                             pk2(v2.x, v2.y), pk2(v2.z, v2.w));
        *(uint4*)(Qs + r * AQSTR + c8) = u;
    }

    float o[2][8][4];
#pragma unroll
    for (int i = 0; i < 2; i++)
#pragma unroll
        for (int j = 0; j < 8; j++)
#pragma unroll
            for (int q = 0; q < 4; q++) o[i][j][q] = 0.f;
    float lsum[4] = {0.f, 0.f, 0.f, 0.f};
    const float c2 = 1.4426950408889634f / 32.0f;  // log2(e)/sqrt(D)

    for (int nt = 0; nt < 16; nt++) {
        __syncthreads();  // prior iter done with Ks/Vs (covers Q stage at nt=0)
        // stage K (128x64)
#pragma unroll
        for (int t = 0; t < 8; t++) {
            int idx = tid + t * 128;
            int r = idx >> 3, c8 = (idx & 7) * 8;
            const float* src = kg + ((size_t)(nt * 128 + r)) * 64 + c8;
            float4 v1 = *(const float4*)(src);
            float4 v2 = *(const float4*)(src + 4);
            uint4 u = make_uint4(pk2(v1.x, v1.y), pk2(v1.z, v1.w),
                                 pk2(v2.x, v2.y), pk2(v2.z, v2.w));
            *(uint4*)(Ks + r * AQSTR + c8) = u;
        }
        // stage V^T (64 hd x 128 s)
#pragma unroll
        for (int t = 0; t < 8; t++) {
            int idx = tid + t * 128;
            int r = idx >> 4, c8 = (idx & 15) * 8;
            const float* src = vg + (size_t)r * SS + nt * 128 + c8;
            float4 v1 = *(const float4*)(src);
            float4 v2 = *(const float4*)(src + 4);
            uint4 u = make_uint4(pk2(v1.x, v1.y), pk2(v1.z, v1.w),
                                 pk2(v2.x, v2.y), pk2(v2.z, v2.w));
            *(uint4*)(Vs + r * AVSTR + c8) = u;
        }
        __syncthreads();

#pragma unroll
        for (int ch = 0; ch < 2; ch++) {
            // S chunk: 32 q-rows x 64 kv-cols, K-dim 64 (4 k16 steps)
            float s_[2][8][4];
#pragma unroll
            for (int i = 0; i < 2; i++)
#pragma unroll
                for (int j = 0; j < 8; j++)
#pragma unroll
                    for (int q = 0; q < 4; q++) s_[i][j][q] = 0.f;

            const uint32_t kChunk = kAddr + (uint32_t)(ch * 64 * AQSTR * 2);
#pragma unroll
            for (int ks = 0; ks < 4; ks++) {
                uint32_t a0[4], a1[4];
                ldsm4(a0, qAddr + ks * 32);
                ldsm4(a1, qAddr + ks * 32 + 16 * AQSTR * 2);
#pragma unroll
                for (int np = 0; np < 4; np++) {
                    uint32_t bf[4];
                    ldsm4(bf, kChunk + ks * 32 + np * 16 * AQSTR * 2);
                    mma16(s_[0][2 * np + 0], a0, bf[0], bf[1]);
                    mma16(s_[0][2 * np + 1], a0, bf[2], bf[3]);
                    mma16(s_[1][2 * np + 0], a1, bf[0], bf[1]);
                    mma16(s_[1][2 * np + 1], a1, bf[2], bf[3]);
                }
            }

            // softmax (fixed max 0) -> fp16 P; sums of rounded values
            uint32_t ph[2][8][2];
#pragma unroll
            for (int mt = 0; mt < 2; mt++) {
                const float* mrp0 = mask +
                    (size_t)(qt * 128 + wid * 32 + mt * 16 + gid) * SS +
                    nt * 128 + ch * 64;
                const float* mrp1 = mrp0 + 8 * SS;
#pragma unroll
                for (int ntl = 0; ntl < 8; ntl++) {
                    float2 m0 = *(const float2*)(mrp0 + ntl * 8 + 2 * tig);
                    float2 m1 = *(const float2*)(mrp1 + ntl * 8 + 2 * tig);
                    float p0 = ex2f((s_[mt][ntl][0] + m0.x) * c2);
                    float p1 = ex2f((s_[mt][ntl][1] + m0.y) * c2);
                    float p2 = ex2f((s_[mt][ntl][2] + m1.x) * c2);
                    float p3 = ex2f((s_[mt][ntl][3] + m1.y) * c2);
                    __half2 h01 = __floats2half2_rn(p0, p1);
                    __half2 h23 = __floats2half2_rn(p2, p3);
                    ph[mt][ntl][0] = *reinterpret_cast<uint32_t*>(&h01);
                    ph[mt][ntl][1] = *reinterpret_cast<uint32_t*>(&h23);
                    float2 f01 = __half22float2(h01);
                    float2 f23 = __half22float2(h23);
                    lsum[mt * 2 + 0] += f01.x + f01.y;
                    lsum[mt * 2 + 1] += f23.x + f23.y;
                }
            }

            // O += P V : V fragments shared across both row-tiles
#pragma unroll
            for (int j = 0; j < 4; j++) {
                uint32_t af0[4], af1[4];
                af0[0] = ph[0][2 * j][0];
                af0[1] = ph[0][2 * j][1];
                af0[2] = ph[0][2 * j + 1][0];
                af0[3] = ph[0][2 * j + 1][1];
                af1[0] = ph[1][2 * j][0];
                af1[1] = ph[1][2 * j][1];
                af1[2] = ph[1][2 * j + 1][0];
                af1[3] = ph[1][2 * j + 1][1];
                const uint32_t kko = (uint32_t)((ch * 64 + 16 * j) * 2);
#pragma unroll
                for (int np = 0; np < 4; np++) {
                    uint32_t bf[4];
                    ldsm4(bf, vAddr + kko + np * 16 * AVSTR * 2);
                    mma16(o[0][2 * np + 0], af0, bf[0], bf[1]);
                    mma16(o[0][2 * np + 1], af0, bf[2], bf[3]);
                    mma16(o[1][2 * np + 0], af1, bf[0], bf[1]);
                    mma16(o[1][2 * np + 1], af1, bf[2], bf[3]);
                }
            }
        }
    }

    // reduce row sums within quad (rows fully owned by this warp)
#pragma unroll
    for (int i = 0; i < 4; i++) {
        lsum[i] += __shfl_xor_sync(0xffffffffu, lsum[i], 1);
        lsum[i] += __shfl_xor_sync(0xffffffffu, lsum[i], 2);
    }

    // write context [b,s,d] (fp32, as R12)
#pragma unroll
    for (int mt = 0; mt < 2; mt++) {
        float inv0 = 1.0f / lsum[mt * 2 + 0];
        float inv1 = 1.0f / lsum[mt * 2 + 1];
        int s0 = qt * 128 + wid * 32 + mt * 16 + gid;
        float* dst0 = ctx + ((size_t)(b * SS + s0)) * DD + h * 64;
        float* dst1 = dst0 + (size_t)8 * DD;
#pragma unroll
        for (int ntl = 0; ntl < 8; ntl++) {
            *(float2*)(dst0 + ntl * 8 + 2 * tig) =
                make_float2(o[mt][ntl][0] * inv0, o[mt][ntl][1] * inv0);
            *(float2*)(dst1 + ntl * 8 + 2 * tig) =
                make_float2(o[mt][ntl][2] * inv1, o[mt][ntl][3] * inv1);
        }
    }
}

// ============================================================================
// Launch
// ============================================================================
extern "C" void kernel_launch(void* const* d_in, const int* in_sizes, int n_in,
                              void* d_out, int out_size) {
    const float* x    = (const float*)d_in[0];
    const float* mask = (const float*)d_in[1];
    const float* Wq   = (const float*)d_in[2];
    const float* Wk   = (const float*)d_in[3];
    const float* Wv   = (const float*)d_in[4];
    const float* Wo   = (const float*)d_in[5];
    float* out = (float*)d_out;

    float *qp, *kp, *vtp, *cp;
    cudaGetSymbolAddress((void**)&qp, g_q);
    cudaGetSymbolAddress((void**)&kp, g_k);
    cudaGetSymbolAddress((void**)&vtp, g_vt);
    cudaGetSymbolAddress((void**)&cp, g_ctx);

    cudaFuncSetAttribute(attn_mma, cudaFuncAttributeMaxDynamicSharedMemorySize,
                         ASMEM_A);

    dim3 gg(DD / 128, MTOT / 128);  // (8, 32)
    gemm_mma<1><<<gg, 256, PSMEM_G>>>(x, Wq, qp);
    gemm_mma<1><<<gg, 256, PSMEM_G>>>(x, Wk, kp);
    gemm_mma<2><<<gg, 256, PSMEM_G>>>(x, Wv, vtp);

    attn_mma<<<dim3(SS / 128, BB * HH), 128, ASMEM_A>>>(mask, cp);

    gemm_mma<0><<<gg, 256, PSMEM_G>>>(cp, Wo, out);
}

// round 17
// speedup vs baseline: 1.6566x; 1.0040x over previous
#include <cuda_runtime.h>
#include <cuda_fp16.h>
#include <cstdint>

#define BB 2
#define SS 2048
#define DD 1024
#define HH 16
#define HDD 64
#define MTOT (BB * SS)

// Scratch: Q/K/V^T fp16 (projection epilogue rounds exactly as R14 staging did),
// ctx fp32.
__device__ __half g_qh[BB * HH * SS * HDD];   // [b,h,s,hd]
__device__ __half g_kh[BB * HH * SS * HDD];   // [b,h,s,hd]
__device__ __half g_vth[BB * HH * HDD * SS];  // [b,h,hd,s]
__device__ float  g_ctx[MTOT * DD];           // [b,s,d]

// ---------------------------------------------------------------- helpers
__device__ __forceinline__ float ex2f(float x) {
    float r;
    asm("ex2.approx.f32 %0, %1;" : "=f"(r) : "f"(x));
    return r;
}
__device__ __forceinline__ uint32_t cvta_s(const void* p) {
    uint32_t a;
    asm("{ .reg .u64 t; cvta.to.shared.u64 t, %1; cvt.u32.u64 %0, t; }"
        : "=r"(a) : "l"(p));
    return a;
}
__device__ __forceinline__ uint32_t pk2(float lo, float hi) {
    __half2 h = __floats2half2_rn(lo, hi);
    return *reinterpret_cast<uint32_t*>(&h);
}
// m16n8k16 f16 MMA, fp32 accum: D += A*B (row.col).
__device__ __forceinline__ void mma16(float* d, const uint32_t* a, uint32_t b0,
                                      uint32_t b1) {
    asm volatile(
        "mma.sync.aligned.m16n8k16.row.col.f32.f16.f16.f32 "
        "{%0,%1,%2,%3}, {%4,%5,%6,%7}, {%8,%9}, {%0,%1,%2,%3};"
        : "+f"(d[0]), "+f"(d[1]), "+f"(d[2]), "+f"(d[3])
        : "r"(a[0]), "r"(a[1]), "r"(a[2]), "r"(a[3]), "r"(b0), "r"(b1));
}
// ldmatrix x4 b16: 4 8x8-fp16 tiles -> 4 regs.
__device__ __forceinline__ void ldsm4(uint32_t* r, uint32_t addr) {
    asm volatile(
        "ldmatrix.sync.aligned.m8n8.x4.shared.b16 {%0,%1,%2,%3}, [%4];"
        : "=r"(r[0]), "=r"(r[1]), "=r"(r[2]), "=r"(r[3])
        : "r"(addr));
}

// ============================================================================
// Projection GEMM (compute identical to R14): C = A * W^T via mma16 + ldmatrix.
// 128x128 tile, BK=16, 256 thr (8 warps, 4x2), per-warp 32x64, 2 CTAs/SM.
// MODE 0: fp32 out[m][n]. MODE 1: fp16 [b,h,s,hd]. MODE 2: fp16 V^T [b,h,hd,s].
// ============================================================================
#define GSTR 24                  // halves per row
#define GTILE (128 * GSTR)       // halves per tile
#define PSMEM_G (4 * GTILE * 2)  // 24576 B

template <int MODE>
__global__ void __launch_bounds__(256, 2)
gemm_mma(const float* __restrict__ A, const float* __restrict__ W,
         void* __restrict__ outp) {
    extern __shared__ __half smh[];
    __half* As[2] = {smh, smh + GTILE};
    __half* Bs[2] = {smh + 2 * GTILE, smh + 3 * GTILE};

    const int tid = threadIdx.x;
    const int lane = tid & 31, wid = tid >> 5;
    const int gid = lane >> 2, tig = lane & 3;
    const int wm = wid & 3, wn = wid >> 2;
    const int m0 = blockIdx.y * 128, n0 = blockIdx.x * 128;

    const float* ap = A + (size_t)m0 * 1024;
    const float* wp = W + (size_t)n0 * 1024;

    const uint32_t smb = cvta_s(smh);
    const uint32_t aAddr =
        smb + ((wm * 32 + (lane & 15)) * GSTR + 8 * (lane >> 4)) * 2;
    const uint32_t bAddr =
        smb + 2 * GTILE * 2 +
        ((wn * 64 + (lane & 7) + 8 * (lane >> 4)) * GSTR +
         8 * ((lane >> 3) & 1)) * 2;

    const int sr = tid >> 1, shf = tid & 1;  // stage: row, col-half

    // stage kt=0 (128 rows x 16 cols per matrix)
    {
        float4 v1 = *(const float4*)(ap + (size_t)sr * 1024 + shf * 8);
        float4 v2 = *(const float4*)(ap + (size_t)sr * 1024 + shf * 8 + 4);
        uint4 u = make_uint4(pk2(v1.x, v1.y), pk2(v1.z, v1.w),
                             pk2(v2.x, v2.y), pk2(v2.z, v2.w));
        *(uint4*)(As[0] + sr * GSTR + shf * 8) = u;
        v1 = *(const float4*)(wp + (size_t)sr * 1024 + shf * 8);
        v2 = *(const float4*)(wp + (size_t)sr * 1024 + shf * 8 + 4);
        u = make_uint4(pk2(v1.x, v1.y), pk2(v1.z, v1.w),
                       pk2(v2.x, v2.y), pk2(v2.z, v2.w));
        *(uint4*)(Bs[0] + sr * GSTR + shf * 8) = u;
    }
    __syncthreads();

    float acc[2][8][4];
#pragma unroll
    for (int i = 0; i < 2; i++)
#pragma unroll
        for (int j = 0; j < 8; j++)
#pragma unroll
            for (int q = 0; q < 4; q++) acc[i][j][q] = 0.f;

    float4 pfa[2], pfw[2];
    for (int kt = 0; kt < 64; kt++) {
        const int buf = kt & 1;
        const uint32_t bufo = buf ? (uint32_t)(GTILE * 2) : 0u;
        if (kt + 1 < 64) {
            const float* a = ap + (kt + 1) * 16;
            const float* w = wp + (kt + 1) * 16;
            pfa[0] = *(const float4*)(a + (size_t)sr * 1024 + shf * 8);
            pfa[1] = *(const float4*)(a + (size_t)sr * 1024 + shf * 8 + 4);
            pfw[0] = *(const float4*)(w + (size_t)sr * 1024 + shf * 8);
            pfw[1] = *(const float4*)(w + (size_t)sr * 1024 + shf * 8 + 4);
        }
        uint32_t a0f[4], a1f[4];
        ldsm4(a0f, aAddr + bufo);
        ldsm4(a1f, aAddr + bufo + 16 * GSTR * 2);
#pragma unroll
        for (int np = 0; np < 4; np++) {
            uint32_t bf[4];
            ldsm4(bf, bAddr + bufo + np * 16 * GSTR * 2);
            mma16(acc[0][2 * np + 0], a0f, bf[0], bf[1]);
            mma16(acc[0][2 * np + 1], a0f, bf[2], bf[3]);
            mma16(acc[1][2 * np + 0], a1f, bf[0], bf[1]);
            mma16(acc[1][2 * np + 1], a1f, bf[2], bf[3]);
        }
        if (kt + 1 < 64) {
            __half* An = As[buf ^ 1];
            __half* Bn = Bs[buf ^ 1];
            __syncthreads();  // everyone done reading buf^1 from kt-1
            uint4 u = make_uint4(pk2(pfa[0].x, pfa[0].y), pk2(pfa[0].z, pfa[0].w),
                                 pk2(pfa[1].x, pfa[1].y), pk2(pfa[1].z, pfa[1].w));
            *(uint4*)(An + sr * GSTR + shf * 8) = u;
            u = make_uint4(pk2(pfw[0].x, pfw[0].y), pk2(pfw[0].z, pfw[0].w),
                           pk2(pfw[1].x, pfw[1].y), pk2(pfw[1].z, pfw[1].w));
            *(uint4*)(Bn + sr * GSTR + shf * 8) = u;
            __syncthreads();
        }
    }

    // epilogue
#pragma unroll
    for (int mt = 0; mt < 2; mt++)
#pragma unroll
        for (int hm = 0; hm < 2; hm++) {
            int mr = m0 + wm * 32 + mt * 16 + gid + hm * 8;
#pragma unroll
            for (int nt = 0; nt < 8; nt++) {
                int nc = n0 + wn * 64 + nt * 8 + 2 * tig;
                float vx = acc[mt][nt][hm * 2 + 0];
                float vy = acc[mt][nt][hm * 2 + 1];
                if (MODE == 0) {
                    *(float2*)((float*)outp + (size_t)mr * 1024 + nc) =
                        make_float2(vx, vy);
                } else if (MODE == 1) {
                    int b = mr >> 11, s = mr & 2047;
                    int h = nc >> 6, hd = nc & 63;
                    // fp16 write == R14 fp32-write + staging-time rne rounding
                    *(uint32_t*)((__half*)outp +
                                 ((size_t)(b * HH + h) * SS + s) * HDD + hd) =
                        pk2(vx, vy);
                } else {
                    int b = mr >> 11, s = mr & 2047;
                    int h = nc >> 6, hd = nc & 63;
                    __half* dst =
                        (__half*)outp + ((size_t)(b * HH + h) * HDD) * SS + s;
                    dst[(size_t)hd * SS] = __float2half_rn(vx);
                    dst[(size_t)(hd + 1) * SS] = __float2half_rn(vy);
                }
            }
        }
}

// ============================================================================
// Flash attention (R14 structure, synchronous staging; staging is now a pure
// fp16 uint4 copy — no conversion). 128 threads (4 warps); warp w owns 32
// q-rows x 128 kv-cols. Numerics identical to R14: fixed-max softmax
// p = exp2((s+mask)*log2e/32) -> fp16 rne (sums of rounded values),
// P accumulator pairs are the f16 A-fragment.
// ============================================================================
#define AQSTR 72    // halves
#define AVSTR 136   // halves
#define OFF_K (128 * AQSTR)
#define OFF_V (2 * 128 * AQSTR)
#define ASMEM_A ((OFF_V + 64 * AVSTR) * 2)  // 54272 B

__global__ void __launch_bounds__(128)
attn_mma(const float* __restrict__ mask, float* __restrict__ ctx) {
    extern __shared__ __half sma[];
    __half* Qs = sma;
    __half* Ks = sma + OFF_K;
    __half* Vs = sma + OFF_V;

    const int tid = threadIdx.x;
    const int lane = tid & 31, wid = tid >> 5;
    const int gid = lane >> 2, tig = lane & 3;
    const int qt = blockIdx.x, bh = blockIdx.y;
    const int b = bh >> 4, h = bh & 15;

    const __half* qg = g_qh + ((size_t)bh * SS + qt * 128) * HDD;
    const __half* kg = g_kh + (size_t)bh * SS * HDD;
    const __half* vg = g_vth + (size_t)bh * HDD * SS;

    // ldmatrix per-lane base addresses (bytes)
    const uint32_t smb = cvta_s(sma);
    const uint32_t qAddr =
        smb + ((wid * 32 + (lane & 15)) * AQSTR + 8 * (lane >> 4)) * 2;
    const uint32_t kAddr =
        smb + OFF_K * 2 +
        (((lane & 7) + 8 * (lane >> 4)) * AQSTR + 8 * ((lane >> 3) & 1)) * 2;
    const uint32_t vAddr =
        smb + OFF_V * 2 +
        (((lane & 7) + 8 * (lane >> 4)) * AVSTR + 8 * ((lane >> 3) & 1)) * 2;

    // stage Q (128x64 fp16), pure copy
#pragma unroll
    for (int t = 0; t < 8; t++) {
        int idx = tid + t * 128;
        int r = idx >> 3, c8 = (idx & 7) * 8;
        *(uint4*)(Qs + r * AQSTR + c8) = *(const uint4*)(qg + (size_t)r * 64 + c8);
    }

    float o[2][8][4];
#pragma unroll
    for (int i = 0; i < 2; i++)
#pragma unroll
        for (int j = 0; j < 8; j++)
#pragma unroll
            for (int q = 0; q < 4; q++) o[i][j][q] = 0.f;
    float lsum[4] = {0.f, 0.f, 0.f, 0.f};
    const float c2 = 1.4426950408889634f / 32.0f;  // log2(e)/sqrt(D)

    for (int nt = 0; nt < 16; nt++) {
        __syncthreads();  // prior iter done with Ks/Vs (covers Q stage at nt=0)
        // stage K (128x64 fp16), pure copy
#pragma unroll
        for (int t = 0; t < 8; t++) {
            int idx = tid + t * 128;
            int r = idx >> 3, c8 = (idx & 7) * 8;
            *(uint4*)(Ks + r * AQSTR + c8) =
                *(const uint4*)(kg + ((size_t)(nt * 128 + r)) * 64 + c8);
        }
        // stage V^T (64 hd x 128 s fp16), pure copy
#pragma unroll
        for (int t = 0; t < 8; t++) {
            int idx = tid + t * 128;
            int r = idx >> 4, c8 = (idx & 15) * 8;
            *(uint4*)(Vs + r * AVSTR + c8) =
                *(const uint4*)(vg + (size_t)r * SS + nt * 128 + c8);
        }
        __syncthreads();

#pragma unroll
        for (int ch = 0; ch < 2; ch++) {
            // S chunk: 32 q-rows x 64 kv-cols, K-dim 64 (4 k16 steps)
            float s_[2][8][4];
#pragma unroll
            for (int i = 0; i < 2; i++)
#pragma unroll
                for (int j = 0; j < 8; j++)
#pragma unroll
                    for (int q = 0; q < 4; q++) s_[i][j][q] = 0.f;

            const uint32_t kChunk = kAddr + (uint32_t)(ch * 64 * AQSTR * 2);
#pragma unroll
            for (int ks = 0; ks < 4; ks++) {
                uint32_t a0[4], a1[4];
                ldsm4(a0, qAddr + ks * 32);
                ldsm4(a1, qAddr + ks * 32 + 16 * AQSTR * 2);
#pragma unroll
                for (int np = 0; np < 4; np++) {
                    uint32_t bf[4];
                    ldsm4(bf, kChunk + ks * 32 + np * 16 * AQSTR * 2);
                    mma16(s_[0][2 * np + 0], a0, bf[0], bf[1]);
                    mma16(s_[0][2 * np + 1], a0, bf[2], bf[3]);
                    mma16(s_[1][2 * np + 0], a1, bf[0], bf[1]);
                    mma16(s_[1][2 * np + 1], a1, bf[2], bf[3]);
                }
            }

            // softmax (fixed max 0) -> fp16 P; sums of rounded values
            uint32_t ph[2][8][2];
#pragma unroll
            for (int mt = 0; mt < 2; mt++) {
                const float* mrp0 = mask +
                    (size_t)(qt * 128 + wid * 32 + mt * 16 + gid) * SS +
                    nt * 128 + ch * 64;
                const float* mrp1 = mrp0 + 8 * SS;
#pragma unroll
                for (int ntl = 0; ntl < 8; ntl++) {
                    float2 m0 = *(const float2*)(mrp0 + ntl * 8 + 2 * tig);
                    float2 m1 = *(const float2*)(mrp1 + ntl * 8 + 2 * tig);
                    float p0 = ex2f((s_[mt][ntl][0] + m0.x) * c2);
                    float p1 = ex2f((s_[mt][ntl][1] + m0.y) * c2);
                    float p2 = ex2f((s_[mt][ntl][2] + m1.x) * c2);
                    float p3 = ex2f((s_[mt][ntl][3] + m1.y) * c2);
                    __half2 h01 = __floats2half2_rn(p0, p1);
                    __half2 h23 = __floats2half2_rn(p2, p3);
                    ph[mt][ntl][0] = *reinterpret_cast<uint32_t*>(&h01);
                    ph[mt][ntl][1] = *reinterpret_cast<uint32_t*>(&h23);
                    float2 f01 = __half22float2(h01);
                    float2 f23 = __half22float2(h23);
                    lsum[mt * 2 + 0] += f01.x + f01.y;
                    lsum[mt * 2 + 1] += f23.x + f23.y;
                }
            }

            // O += P V : V fragments shared across both row-tiles
#pragma unroll
            for (int j = 0; j < 4; j++) {
                uint32_t af0[4], af1[4];
                af0[0] = ph[0][2 * j][0];
                af0[1] = ph[0][2 * j][1];
                af0[2] = ph[0][2 * j + 1][0];
                af0[3] = ph[0][2 * j + 1][1];
                af1[0] = ph[1][2 * j][0];
                af1[1] = ph[1][2 * j][1];
                af1[2] = ph[1][2 * j + 1][0];
                af1[3] = ph[1][2 * j + 1][1];
                const uint32_t kko = (uint32_t)((ch * 64 + 16 * j) * 2);
#pragma unroll
                for (int np = 0; np < 4; np++) {
                    uint32_t bf[4];
                    ldsm4(bf, vAddr + kko + np * 16 * AVSTR * 2);
                    mma16(o[0][2 * np + 0], af0, bf[0], bf[1]);
                    mma16(o[0][2 * np + 1], af0, bf[2], bf[3]);
                    mma16(o[1][2 * np + 0], af1, bf[0], bf[1]);
                    mma16(o[1][2 * np + 1], af1, bf[2], bf[3]);
                }
            }
        }
    }

    // reduce row sums within quad (rows fully owned by this warp)
#pragma unroll
    for (int i = 0; i < 4; i++) {
        lsum[i] += __shfl_xor_sync(0xffffffffu, lsum[i], 1);
        lsum[i] += __shfl_xor_sync(0xffffffffu, lsum[i], 2);
    }

    // write context [b,s,d] (fp32)
#pragma unroll
    for (int mt = 0; mt < 2; mt++) {
        float inv0 = 1.0f / lsum[mt * 2 + 0];
        float inv1 = 1.0f / lsum[mt * 2 + 1];
        int s0 = qt * 128 + wid * 32 + mt * 16 + gid;
        float* dst0 = ctx + ((size_t)(b * SS + s0)) * DD + h * 64;
        float* dst1 = dst0 + (size_t)8 * DD;
#pragma unroll
        for (int ntl = 0; ntl < 8; ntl++) {
            *(float2*)(dst0 + ntl * 8 + 2 * tig) =
                make_float2(o[mt][ntl][0] * inv0, o[mt][ntl][1] * inv0);
            *(float2*)(dst1 + ntl * 8 + 2 * tig) =
                make_float2(o[mt][ntl][2] * inv1, o[mt][ntl][3] * inv1);
        }
    }
}

// ============================================================================
// Launch
// ============================================================================
extern "C" void kernel_launch(void* const* d_in, const int* in_sizes, int n_in,
                              void* d_out, int out_size) {
    const float* x    = (const float*)d_in[0];
    const float* mask = (const float*)d_in[1];
    const float* Wq   = (const float*)d_in[2];
    const float* Wk   = (const float*)d_in[3];
    const float* Wv   = (const float*)d_in[4];
    const float* Wo   = (const float*)d_in[5];
    float* out = (float*)d_out;

    __half *qh, *kh, *vth;
    float* cp;
    cudaGetSymbolAddress((void**)&qh, g_qh);
    cudaGetSymbolAddress((void**)&kh, g_kh);
    cudaGetSymbolAddress((void**)&vth, g_vth);
    cudaGetSymbolAddress((void**)&cp, g_ctx);

    cudaFuncSetAttribute(attn_mma, cudaFuncAttributeMaxDynamicSharedMemorySize,
                         ASMEM_A);

    dim3 gg(DD / 128, MTOT / 128);  // (8, 32)
    gemm_mma<1><<<gg, 256, PSMEM_G>>>(x, Wq, qh);
    gemm_mma<1><<<gg, 256, PSMEM_G>>>(x, Wk, kh);
    gemm_mma<2><<<gg, 256, PSMEM_G>>>(x, Wv, vth);

    attn_mma<<<dim3(SS / 128, BB * HH), 128, ASMEM_A>>>(mask, cp);

    gemm_mma<0><<<gg, 256, PSMEM_G>>>(cp, Wo, out);
}